// round 4
// baseline (speedup 1.0000x reference)
#include <cuda_runtime.h>
#include <math.h>

#define BB   128   // batch
#define TSEQ 512   // sequence length
#define DD   256   // model dim
#define HH   256   // lstm hidden
#define NG   1024  // 4*HH
#define NBLK 384   // persistent LSTM grid (6 layer-steps x 64 tiles)

typedef unsigned long long u64;

// ---- packed f32x2 helpers ----
__device__ __forceinline__ u64 pk2(float lo, float hi) {
    u64 r; asm("mov.b64 %0, {%1,%2};" : "=l"(r) : "f"(lo), "f"(hi)); return r;
}
__device__ __forceinline__ u64 ff2(u64 a, u64 b, u64 c) {
    u64 d; asm("fma.rn.f32x2 %0, %1, %2, %3;" : "=l"(d) : "l"(a), "l"(b), "l"(c));
    return d;
}
__device__ __forceinline__ float2 up2(u64 v) {
    float2 f; asm("mov.b64 {%0,%1}, %2;" : "=f"(f.x), "=f"(f.y) : "l"(v)); return f;
}

// ---------------- device scratch ----------------
__device__ float g_x[BB * TSEQ * DD];
__device__ float g_feats[BB * TSEQ * DD];
__device__ float g_Wt2[2 * 3 * 512 * NG * 2];  // dup pairs: [dl][k][(col*4+g)][2]
__device__ float g_cur[2 * 2 * 2 * BB * DD];   // [dir][stage][parity][b][d]
__device__ float g_h[2 * 3 * 2 * BB * HH];     // [dl][pingpong][b][h]
__device__ float g_c[2 * 3 * BB * HH];
__device__ unsigned g_sync;

// ---------------- embedding gather ----------------
__global__ void k_embed(const int* __restrict__ tokens, const float* __restrict__ E) {
    int row = blockIdx.x;
    int tok = tokens[row];
    const float4* src = reinterpret_cast<const float4*>(E) + (size_t)tok * (DD / 4);
    float4* dst = reinterpret_cast<float4*>(g_x) + (size_t)row * (DD / 4);
    dst[threadIdx.x] = src[threadIdx.x];
}

// ---------------- conv bank (FFMA2, pre-paired x) ----------------
__global__ void __launch_bounds__(256, 2) k_conv(
    const float* __restrict__ W3, const float* __restrict__ W5,
    const float* __restrict__ W7, const float* __restrict__ bconv, int iter)
{
    const int o  = threadIdx.x;
    const int t0 = blockIdx.x * 16;
    const int b  = blockIdx.y;

    __shared__ u64 sxp[DD][15];   // [c][pair i] = {x[t0-3+i], x[t0+5+i]}, pad 15
    const float* xb = g_x + (size_t)b * TSEQ * DD;
    float xr[22];
#pragma unroll
    for (int r = 0; r < 22; ++r) {
        int tg = t0 - 3 + r;
        xr[r] = (tg >= 0 && tg < TSEQ) ? xb[(size_t)tg * DD + o] : 0.f;
    }
#pragma unroll
    for (int i = 0; i < 14; ++i) sxp[o][i] = pk2(xr[i], xr[i + 8]);
    __syncthreads();

    u64 acc3[8], acc5[8], acc7[8];
    const u64 z = pk2(0.f, 0.f);
#pragma unroll
    for (int i = 0; i < 8; ++i) { acc3[i] = z; acc5[i] = z; acc7[i] = z; }

    const float* W3i = W3 + (size_t)iter * 3 * DD * DD + o;
    const float* W5i = W5 + (size_t)iter * 5 * DD * DD + o;
    const float* W7i = W7 + (size_t)iter * 7 * DD * DD + o;

    for (int c = 0; c < DD; ++c) {
        u64 xp[14];
#pragma unroll
        for (int i = 0; i < 14; ++i) xp[i] = sxp[c][i];

#pragma unroll
        for (int k = 0; k < 7; ++k) {
            float w = W7i[((size_t)k * DD + c) * DD];
            u64 ww = pk2(w, w);
#pragma unroll
            for (int i = 0; i < 8; ++i) acc7[i] = ff2(xp[i + k], ww, acc7[i]);
        }
#pragma unroll
        for (int k = 0; k < 5; ++k) {
            float w = W5i[((size_t)k * DD + c) * DD];
            u64 ww = pk2(w, w);
#pragma unroll
            for (int i = 0; i < 8; ++i) acc5[i] = ff2(xp[i + k + 1], ww, acc5[i]);
        }
#pragma unroll
        for (int k = 0; k < 3; ++k) {
            float w = W3i[((size_t)k * DD + c) * DD];
            u64 ww = pk2(w, w);
#pragma unroll
            for (int i = 0; i < 8; ++i) acc3[i] = ff2(xp[i + k + 2], ww, acc3[i]);
        }
    }

    float b3 = bconv[(iter * 3 + 0) * DD + o];
    float b5 = bconv[(iter * 3 + 1) * DD + o];
    float b7 = bconv[(iter * 3 + 2) * DD + o];
    float* fb = g_feats + ((size_t)b * TSEQ + t0) * DD + o;
#pragma unroll
    for (int i = 0; i < 8; ++i) {
        float2 a3 = up2(acc3[i]), a5 = up2(acc5[i]), a7 = up2(acc7[i]);
        float2 res = up2(sxp[o][i + 3]);   // {x[t0+i], x[t0+i+8]}
        fb[(size_t)i * DD] = tanhf(a3.x + b3) + tanhf(a5.x + b5) +
                             tanhf(a7.x + b7) + res.x;
        fb[(size_t)(i + 8) * DD] = tanhf(a3.y + b3) + tanhf(a5.y + b5) +
                                   tanhf(a7.y + b7) + res.y;
    }
}

// ---------------- layernorm ----------------
__global__ void k_ln(const float* __restrict__ gamma, const float* __restrict__ beta, int iter) {
    int wid = threadIdx.x >> 5, lane = threadIdx.x & 31;
    int row = blockIdx.x * 8 + wid;
    const float4* f = reinterpret_cast<const float4*>(g_feats + (size_t)row * DD);
    float4 v0 = f[lane];
    float4 v1 = f[32 + lane];
    float s = v0.x + v0.y + v0.z + v0.w + v1.x + v1.y + v1.z + v1.w;
    float q = v0.x*v0.x + v0.y*v0.y + v0.z*v0.z + v0.w*v0.w +
              v1.x*v1.x + v1.y*v1.y + v1.z*v1.z + v1.w*v1.w;
#pragma unroll
    for (int ofs = 16; ofs; ofs >>= 1) {
        s += __shfl_xor_sync(0xffffffffu, s, ofs);
        q += __shfl_xor_sync(0xffffffffu, q, ofs);
    }
    float mean = s * (1.f / 256.f);
    float var  = q * (1.f / 256.f) - mean * mean;
    float rstd = rsqrtf(var + 1e-3f);

    const float* ga = gamma + iter * DD;
    const float* be = beta + iter * DD;
    float4* xo = reinterpret_cast<float4*>(g_x + (size_t)row * DD);
    int c0 = lane * 4;
    float4 r0, r1;
    r0.x = (v0.x - mean) * rstd * ga[c0 + 0] + be[c0 + 0];
    r0.y = (v0.y - mean) * rstd * ga[c0 + 1] + be[c0 + 1];
    r0.z = (v0.z - mean) * rstd * ga[c0 + 2] + be[c0 + 2];
    r0.w = (v0.w - mean) * rstd * ga[c0 + 3] + be[c0 + 3];
    r1.x = (v1.x - mean) * rstd * ga[128 + c0 + 0] + be[128 + c0 + 0];
    r1.y = (v1.y - mean) * rstd * ga[128 + c0 + 1] + be[128 + c0 + 1];
    r1.z = (v1.z - mean) * rstd * ga[128 + c0 + 2] + be[128 + c0 + 2];
    r1.w = (v1.w - mean) * rstd * ga[128 + c0 + 3] + be[128 + c0 + 3];
    xo[lane] = r0;
    xo[32 + lane] = r1;
}

// ---------------- weight pre-transpose with duplication ----------------
// g_Wt2[dl][k][(col*4+g)*2 + d] = W[dl][k][g*256+col]  (d=0,1 duplicate)
__global__ void k_transpose(const float* __restrict__ Wx, const float* __restrict__ Wh) {
    int idx = blockIdx.x * 256 + threadIdx.x;
    const int TOT = 2 * 3 * 512 * NG * 2;
    if (idx >= TOT) return;
    int dl   = idx / (512 * NG * 2);
    int rem  = idx % (512 * NG * 2);
    int k    = rem / (NG * 2);
    int cp2  = rem % (NG * 2);
    int pair = cp2 >> 1;          // col*4+g
    int col  = pair >> 2, g = pair & 3;
    int n = g * 256 + col;
    float v = (k < 256) ? Wx[(size_t)dl * 256 * NG + (size_t)k * NG + n]
                        : Wh[(size_t)dl * 256 * NG + (size_t)(k - 256) * NG + n];
    g_Wt2[idx] = v;
}

__global__ void k_zero() {
    int i = blockIdx.x * 256 + threadIdx.x;
    if (i < 2 * 3 * 2 * BB * HH) g_h[i] = 0.f;
    if (i < 2 * 3 * BB * HH)     g_c[i] = 0.f;
    if (i == 0) g_sync = 0u;
}

// ---------------- persistent wavefront LSTM (FFMA2, dup-w, prefetch pipe) --
// 384 blocks x 128 threads. Block tile 32m x 16 cols (x4 gates).
// Thread: j = tid>>3 (col), mg = tid&7 (4 m-rows). Inner loop: 12 issues/16 FMA-cyc.
__global__ void __launch_bounds__(128, 3) k_lstm_persist(
    const float* __restrict__ blstm, float* __restrict__ out)
{
    const int bx    = blockIdx.x;
    const int ls    = bx >> 6;
    const int dir   = ls & 1;
    const int layer = ls >> 1;
    const int sub   = bx & 63;
    const int j0    = (sub & 15) * 16;
    const int m0    = (sub >> 4) * 32;
    const int tid   = threadIdx.x;
    const int j     = tid >> 3;          // 0..15 col
    const int mg    = tid & 7;           // 0..7 -> 4 m-rows each
    const int dl    = dir * 3 + layer;

    __shared__ float sA[32][34];     // [k][m]
    __shared__ float sW[32][128];    // [k][(col,g) dup pairs]

    const float* Wbase = g_Wt2 + (size_t)dl * 512 * (NG * 2) + j0 * 8;
    const int col = j0 + j;
    const float* bbias = blstm + (size_t)dl * NG;
    const float bi  = bbias[col];
    const float bf_ = bbias[256 + col];
    const float bg  = bbias[512 + col];
    const float bo  = bbias[768 + col];
    float* cbuf = g_c + (size_t)dl * BB * HH;

    // fill roles
    const int fm = tid >> 2;          // 0..31 m within tile
    const int fk = (tid & 3) * 8;     // k base within chunk (A fill)
    const int fmg = m0 + fm;

    // W fill per-thread fixed (k,q) per round r: e4 = tid + r*128
    const unsigned nb = gridDim.x;
    const int lprev = (layer > 0) ? (layer - 1) : 0;

    for (int w = 0; w < TSEQ + 2; ++w) {
        const int t = w - layer;
        if (t >= 0 && t < TSEQ) {
            const int tt = dir ? (TSEQ - 1 - t) : t;
            const int rp = t & 1, wp = rp ^ 1;
            const float* hin = g_h + (size_t)(dl * 2 + rp) * BB * HH;
            const float* cursrc = g_cur +
                (size_t)((dir * 2 + lprev) * 2 + (t & 1)) * BB * DD;
            float* curdst = g_cur +
                (size_t)((dir * 2 + layer) * 2 + (t & 1)) * BB * DD;
            const float* gx_row = g_x + ((size_t)fmg * TSEQ + tt) * DD;

            u64 acc[4][2];
            const u64 zz = pk2(0.f, 0.f);
#pragma unroll
            for (int g = 0; g < 4; ++g) { acc[g][0] = zz; acc[g][1] = zz; }

            // ---- prefetch chunk 0 into regs ----
            float4 va0, va1, vw[8];
            {
                int kk = fk;  // kc=0
                const float* src = (layer == 0) ? (gx_row + kk)
                                                : (cursrc + (size_t)fmg * DD + kk);
                va0 = *reinterpret_cast<const float4*>(src);
                va1 = *reinterpret_cast<const float4*>(src + 4);
#pragma unroll
                for (int r = 0; r < 8; ++r) {
                    int e4 = tid + r * 128;
                    int k = e4 >> 5, q = e4 & 31;
                    vw[r] = *reinterpret_cast<const float4*>(
                        Wbase + (size_t)k * (NG * 2) + q * 4);
                }
            }

            for (int kc = 0; kc < 512; kc += 32) {
                __syncthreads();   // prior compute (or barrier) done
                // stage regs -> smem
                sA[fk + 0][fm] = va0.x; sA[fk + 1][fm] = va0.y;
                sA[fk + 2][fm] = va0.z; sA[fk + 3][fm] = va0.w;
                sA[fk + 4][fm] = va1.x; sA[fk + 5][fm] = va1.y;
                sA[fk + 6][fm] = va1.z; sA[fk + 7][fm] = va1.w;
#pragma unroll
                for (int r = 0; r < 8; ++r) {
                    int e4 = tid + r * 128;
                    int k = e4 >> 5, q = e4 & 31;
                    *reinterpret_cast<float4*>(&sW[k][q * 4]) = vw[r];
                }
                __syncthreads();

                // prefetch next chunk
                if (kc + 32 < 512) {
                    int kk = kc + 32 + fk;
                    if (kk < 256) {
                        const float* src = (layer == 0) ? (gx_row + kk)
                                                        : (cursrc + (size_t)fmg * DD + kk);
                        va0 = *reinterpret_cast<const float4*>(src);
                        va1 = *reinterpret_cast<const float4*>(src + 4);
                    } else {
                        const float4* src = reinterpret_cast<const float4*>(
                            hin + (size_t)fmg * HH + (kk - 256));
                        va0 = __ldcg(src);
                        va1 = __ldcg(src + 1);
                    }
#pragma unroll
                    for (int r = 0; r < 8; ++r) {
                        int e4 = tid + r * 128;
                        int k = e4 >> 5, q = e4 & 31;
                        vw[r] = *reinterpret_cast<const float4*>(
                            Wbase + (size_t)(kc + 32 + k) * (NG * 2) + q * 4);
                    }
                }

                // compute: 12 issues / 16 FMA-pipe cycles per k
#pragma unroll
                for (int k = 0; k < 32; ++k) {
                    u64 a01 = *reinterpret_cast<const u64*>(&sA[k][mg * 4]);
                    u64 a23 = *reinterpret_cast<const u64*>(&sA[k][mg * 4 + 2]);
                    ulonglong2 w01 = *reinterpret_cast<const ulonglong2*>(&sW[k][j * 8]);
                    ulonglong2 w23 = *reinterpret_cast<const ulonglong2*>(&sW[k][j * 8 + 4]);
                    acc[0][0] = ff2(a01, w01.x, acc[0][0]);
                    acc[0][1] = ff2(a23, w01.x, acc[0][1]);
                    acc[1][0] = ff2(a01, w01.y, acc[1][0]);
                    acc[1][1] = ff2(a23, w01.y, acc[1][1]);
                    acc[2][0] = ff2(a01, w23.x, acc[2][0]);
                    acc[2][1] = ff2(a23, w23.x, acc[2][1]);
                    acc[3][0] = ff2(a01, w23.y, acc[3][0]);
                    acc[3][1] = ff2(a23, w23.y, acc[3][1]);
                }
            }

            float* hout = g_h + (size_t)(dl * 2 + wp) * BB * HH;
#pragma unroll
            for (int p = 0; p < 2; ++p) {
                float2 zi = up2(acc[0][p]);
                float2 zf = up2(acc[1][p]);
                float2 zg = up2(acc[2][p]);
                float2 zo = up2(acc[3][p]);
#pragma unroll
                for (int h2 = 0; h2 < 2; ++h2) {
                    int m = m0 + mg * 4 + p * 2 + h2;
                    float vzi = (h2 ? zi.y : zi.x) + bi;
                    float vzf = (h2 ? zf.y : zf.x) + bf_;
                    float vzg = (h2 ? zg.y : zg.x) + bg;
                    float vzo = (h2 ? zo.y : zo.x) + bo;
                    float ig = 1.f / (1.f + expf(-vzi));
                    float fg = 1.f / (1.f + expf(-vzf));
                    float gg = tanhf(vzg);
                    float og = 1.f / (1.f + expf(-vzo));
                    float cp = cbuf[(size_t)m * HH + col];
                    float cn = fg * cp + ig * gg;
                    float hn = og * tanhf(cn);
                    cbuf[(size_t)m * HH + col] = cn;
                    hout[(size_t)m * HH + col] = hn;
                    float ain = (layer == 0)
                        ? g_x[((size_t)m * TSEQ + tt) * DD + col]
                        : __ldcg(cursrc + (size_t)m * DD + col);
                    float cu = ain + hn;
                    if (layer == 2)
                        out[((size_t)m * TSEQ + tt) * 512 + dir * 256 + col] = cu;
                    else
                        curdst[(size_t)m * DD + col] = cu;
                }
            }
        }

        // ---- grid barrier (release/acquire, CG-style) ----
        __syncthreads();
        if (tid == 0) {
            unsigned* sp = &g_sync;
            asm volatile("red.release.gpu.add.u32 [%0], %1;"
                         :: "l"(sp), "r"(1u) : "memory");
            unsigned target = nb * (unsigned)(w + 1);
            unsigned v;
            do {
                asm volatile("ld.acquire.gpu.u32 %0, [%1];"
                             : "=r"(v) : "l"(sp) : "memory");
                if (v >= target) break;
                __nanosleep(32);
            } while (true);
        }
        __syncthreads();
    }
}

// ---------------- final states ----------------
__global__ void k_states(float* __restrict__ out) {
    int idx = blockIdx.x * 256 + threadIdx.x;
    if (idx >= 2 * 3 * BB * HH) return;
    int j  = idx & 255;
    int m  = (idx >> 8) & 127;
    int dl = idx >> 15;
    const size_t SEQ = (size_t)BB * TSEQ * 512;
    const size_t SH  = 2 * 3 * BB * HH;
    out[SEQ + idx]      = g_h[(size_t)(dl * 2 + 0) * BB * HH + (size_t)m * HH + j];
    out[SEQ + SH + idx] = g_c[(size_t)dl * BB * HH + (size_t)m * HH + j];
}

// ---------------- launch ----------------
extern "C" void kernel_launch(void* const* d_in, const int* in_sizes, int n_in,
                              void* d_out, int out_size) {
    const int*   tokens = (const int*)d_in[0];
    const float* E      = (const float*)d_in[1];
    const float* W3     = (const float*)d_in[2];
    const float* W5     = (const float*)d_in[3];
    const float* W7     = (const float*)d_in[4];
    const float* bconv  = (const float*)d_in[5];
    const float* gamma  = (const float*)d_in[6];
    const float* beta   = (const float*)d_in[7];
    const float* Wx     = (const float*)d_in[8];
    const float* Wh     = (const float*)d_in[9];
    const float* blstm  = (const float*)d_in[10];
    float* out = (float*)d_out;

    k_embed<<<BB * TSEQ, 64>>>(tokens, E);
    for (int it = 0; it < 2; ++it) {
        k_conv<<<dim3(TSEQ / 16, BB), 256>>>(W3, W5, W7, bconv, it);
        k_ln<<<BB * TSEQ / 8, 256>>>(gamma, beta, it);
    }
    k_transpose<<<(2 * 3 * 512 * NG * 2 + 255) / 256, 256>>>(Wx, Wh);
    k_zero<<<1536, 256>>>();
    k_lstm_persist<<<NBLK, 128>>>(blstm, out);
    k_states<<<768, 256>>>(out);
}